// round 14
// baseline (speedup 1.0000x reference)
#include <cuda_runtime.h>
#include <cuda_fp16.h>
#include <cstdint>

#define DIMM   1024
#define NHEADS 16
#define HD     64
#define BATCH  2
#define SEQ    2048
#define MROWS  (BATCH*SEQ)   /* 4096 */
#define WFLOATS (DIMM*DIMM)

// Scratch (allocation-free)
__device__ __half g_qh[MROWS*DIMM];
__device__ __half g_kh[MROWS*DIMM];
__device__ __half g_vh[MROWS*DIMM];
__device__ __half g_att[MROWS*DIMM];
__device__ __half g_xh[MROWS*DIMM];
__device__ __half g_wh[4*WFLOATS];

// ===========================================================================
// Helpers
// ===========================================================================
__device__ __forceinline__ uint32_t smem_u32(const void* p) {
    uint32_t a;
    asm("{ .reg .u64 t; cvta.to.shared.u64 t, %1; cvt.u32.u64 %0, t; }" : "=r"(a) : "l"(p));
    return a;
}
__device__ __forceinline__ void cp_async16(uint32_t dst, const void* src) {
    asm volatile("cp.async.cg.shared.global [%0], [%1], 16;" :: "r"(dst), "l"(src) : "memory");
}
#define CP_COMMIT()  asm volatile("cp.async.commit_group;" ::: "memory")
#define CP_WAIT(n)   asm volatile("cp.async.wait_group %0;" :: "n"(n) : "memory")

__device__ __forceinline__ uint32_t pack_h2(float a, float b) {
    __half2 h = __floats2half2_rn(a, b);
    return *(uint32_t*)&h;
}
// fp16 m16n8k16: D += A*B
__device__ __forceinline__ void mma16(float* c, const uint32_t* a, const uint32_t* b) {
    asm volatile(
        "mma.sync.aligned.m16n8k16.row.col.f32.f16.f16.f32 "
        "{%0,%1,%2,%3}, {%4,%5,%6,%7}, {%8,%9}, {%0,%1,%2,%3};"
        : "+f"(c[0]), "+f"(c[1]), "+f"(c[2]), "+f"(c[3])
        : "r"(a[0]), "r"(a[1]), "r"(a[2]), "r"(a[3]), "r"(b[0]), "r"(b[1]));
}
__device__ __forceinline__ void ldsm4(uint32_t& r0, uint32_t& r1, uint32_t& r2, uint32_t& r3,
                                      uint32_t addr) {
    asm volatile("ldmatrix.sync.aligned.m8n8.x4.shared.b16 {%0,%1,%2,%3}, [%4];"
                 : "=r"(r0), "=r"(r1), "=r"(r2), "=r"(r3) : "r"(addr));
}
__device__ __forceinline__ void ldsm4t(uint32_t& r0, uint32_t& r1, uint32_t& r2, uint32_t& r3,
                                       uint32_t addr) {
    asm volatile("ldmatrix.sync.aligned.m8n8.x4.trans.shared.b16 {%0,%1,%2,%3}, [%4];"
                 : "=r"(r0), "=r"(r1), "=r"(r2), "=r"(r3) : "r"(addr));
}

// FMA-pipe exp: e^(s * 0.125). Clamps low (masked entries -> ~0).
__device__ __forceinline__ float fexp_s(float s) {
    float y = s * 0.18033688011112042f;
    y = fmaxf(y, -100.0f);
    float t = __fadd_rn(y, 12582912.0f);
    float f = __fsub_rn(y, __fsub_rn(t, 12582912.0f));
    int   e = __float_as_int(t) << 23;
    float p = 1.3333558146e-3f;
    p = fmaf(p, f, 9.618129107e-3f);
    p = fmaf(p, f, 5.550410866e-2f);
    p = fmaf(p, f, 2.402265069e-1f);
    p = fmaf(p, f, 6.931471806e-1f);
    p = fmaf(p, f, 1.0f);
    return __int_as_float(__float_as_int(p) + e);
}

// ===========================================================================
// Fused fp32 -> fp16 conversion: y=0 -> x (n4x), y=1..4 -> weights (n4w each)
// ===========================================================================
__global__ __launch_bounds__(256) void round_all(
    const float* __restrict__ x,
    const float* __restrict__ w0, const float* __restrict__ w1,
    const float* __restrict__ w2, const float* __restrict__ w3,
    __half* __restrict__ xh, __half* __restrict__ wh, int n4x, int n4w)
{
    const int y = blockIdx.y;
    const float* in;
    __half* o;
    int n4;
    if (y == 0) { in = x; o = xh; n4 = n4x; }
    else        { in = (y == 1) ? w0 : (y == 2) ? w1 : (y == 3) ? w2 : w3;
                  o = wh + (size_t)(y - 1) * WFLOATS; n4 = n4w; }
    int i = blockIdx.x * blockDim.x + threadIdx.x;
    if (i < n4) {
        float4 v = ((const float4*)in)[i];
        uint2 w;
        w.x = pack_h2(v.x, v.y);
        w.y = pack_h2(v.z, v.w);
        ((uint2*)o)[i] = w;
    }
}

// ===========================================================================
// fp16 mma.sync GEMM with ldmatrix fragments.
// CTA 128x128, 8 warps (2m x 4n), BK=32 halves, 3-stage cp.async,
// SINGLE barrier per ktile.
// ===========================================================================
#define BK    32
#define KW    20
#define GST   3
#define GSTAGE_U32 (2*128*KW)
#define GSMEM_BYTES (GST * GSTAGE_U32 * 4)   /* 61440 */
#define KT    (DIMM / BK)

template<bool HALF_OUT>
__global__ __launch_bounds__(256, 2) void gemm_h(
    const __half* __restrict__ A,
    const __half* __restrict__ B0, const __half* __restrict__ B1, const __half* __restrict__ B2,
    void* __restrict__ C0, void* __restrict__ C1, void* __restrict__ C2)
{
    extern __shared__ uint32_t sm[];
    const int tid  = threadIdx.x;
    const int wid  = tid >> 5;
    const int lane = tid & 31;
    const int wm   = wid >> 2;
    const int wn   = wid & 3;
    const int r0   = lane >> 2;
    const int q4   = lane & 3;
    const int g    = lane >> 3;
    const int lr   = lane & 7;

    const __half* Bz = (blockIdx.z == 0) ? B0 : (blockIdx.z == 1) ? B1 : B2;
    void*         Cz = (blockIdx.z == 0) ? C0 : (blockIdx.z == 1) ? C1 : C2;

    const __half* Ag = A  + (size_t)(blockIdx.y * 128) * DIMM;
    const __half* Bg = Bz + (size_t)(blockIdx.x * 128) * DIMM;
    const uint32_t sbase = smem_u32(sm);

    const uint32_t a_off = ((wm * 64 + (g & 1) * 8 + lr) * KW + (g >> 1) * 4) * 4;
    const uint32_t b_off = (128 * KW + (wn * 32 + (g >> 1) * 8 + lr) * KW + (g & 1) * 4) * 4;

    auto load_tile = [&](int kt) {
        const int s = kt % GST;
        uint32_t ab = sbase + s * GSTAGE_U32 * 4;
        uint32_t bb = ab + 128 * KW * 4;
#pragma unroll
        for (int i = 0; i < 2; i++) {
            int idx = i * 256 + tid;
            int row = idx >> 2, seg = idx & 3;
            cp_async16(ab + (row * KW + seg * 4) * 4,
                       Ag + (size_t)row * DIMM + kt * BK + seg * 8);
        }
#pragma unroll
        for (int i = 0; i < 2; i++) {
            int idx = i * 256 + tid;
            int row = idx >> 2, seg = idx & 3;
            cp_async16(bb + (row * KW + seg * 4) * 4,
                       Bg + (size_t)row * DIMM + kt * BK + seg * 8);
        }
        CP_COMMIT();
    };

    float c[4][4][4];
#pragma unroll
    for (int i = 0; i < 4; i++)
#pragma unroll
        for (int j = 0; j < 4; j++)
#pragma unroll
            for (int u = 0; u < 4; u++) c[i][j][u] = 0.f;

    load_tile(0);
    load_tile(1);

    for (int kt = 0; kt < KT; kt++) {
        if (kt + 1 < KT) { CP_WAIT(1); } else { CP_WAIT(0); }
        __syncthreads();     // kt resident for all warps; all warps done reading stage (kt+2)%3
        if (kt + 2 < KT) load_tile(kt + 2);

        const uint32_t stage = sbase + (kt % GST) * GSTAGE_U32 * 4;
#pragma unroll
        for (int st = 0; st < 2; st++) {
            const uint32_t koff = st * 8 * 4;
            uint32_t a[4][4], b[4][2];
#pragma unroll
            for (int i = 0; i < 4; i++)
                ldsm4(a[i][0], a[i][1], a[i][2], a[i][3],
                      stage + a_off + (i * 16 * KW) * 4 + koff);
#pragma unroll
            for (int jp = 0; jp < 2; jp++)
                ldsm4(b[2*jp][0], b[2*jp][1], b[2*jp+1][0], b[2*jp+1][1],
                      stage + b_off + (jp * 16 * KW) * 4 + koff);
#pragma unroll
            for (int i = 0; i < 4; i++)
#pragma unroll
                for (int j = 0; j < 4; j++)
                    mma16(c[i][j], a[i], b[j]);
        }
    }

    const size_t crow = (size_t)(blockIdx.y * 128 + wm * 64);
    const int    ccol = blockIdx.x * 128 + wn * 32;
#pragma unroll
    for (int i = 0; i < 4; i++)
#pragma unroll
        for (int j = 0; j < 4; j++) {
            int lrr = i * 16 + r0;
            int col = j * 8 + 2 * q4;
            if (HALF_OUT) {
                __half* Ch = (__half*)Cz + (crow + lrr) * DIMM + ccol + col;
                *(uint32_t*)Ch              = pack_h2(c[i][j][0], c[i][j][1]);
                *(uint32_t*)(Ch + 8 * DIMM) = pack_h2(c[i][j][2], c[i][j][3]);
            } else {
                float* Cf = (float*)Cz + (crow + lrr) * DIMM + ccol + col;
                *(float2*)Cf              = make_float2(c[i][j][0], c[i][j][1]);
                *(float2*)(Cf + 8 * DIMM) = make_float2(c[i][j][2], c[i][j][3]);
            }
        }
}

// ===========================================================================
// Fused causal flash attention, all-fp16, register-P, 3-stage KV ring,
// one barrier per tile, DEFERRED row-sum reduction (outside the loop).
// ===========================================================================
#define QPH 36
#define VPH 36
#define FSW  (2*64*QPH)
#define FSMEM_WORDS (3*FSW)
#define FSMEM_BYTES (FSMEM_WORDS * 4)   /* 55296 */

__global__ __launch_bounds__(128, 4) void flash_h(
    const __half* __restrict__ gq, const __half* __restrict__ gk,
    const __half* __restrict__ gv, __half* __restrict__ go)
{
    extern __shared__ uint32_t fsm[];

    const int qb  = gridDim.x - 1 - blockIdx.x;
    const int bh  = blockIdx.y;
    const int b   = bh >> 4;
    const int h   = bh & 15;
    const int tid = threadIdx.x;
    const int wid = tid >> 5;
    const int lane = tid & 31;
    const int r0 = lane >> 2;
    const int q4 = lane & 3;
    const int g  = lane >> 3;
    const int lr = lane & 7;
    const size_t hbase = (size_t)b * SEQ * DIMM + (size_t)h * HD;
    const uint32_t sbase = smem_u32(fsm);

    const uint32_t koff_b = (((g >> 1) * 8 + lr) * QPH + (g & 1) * 4) * 4;
    const uint32_t voff_b = (((g & 1) * 8 + lr) * VPH + (g >> 1) * 4) * 4;

    auto load_kv = [&](int t) {
        const int s = t % 3;
        const uint32_t kb = sbase + (s * FSW) * 4;
        const uint32_t vb = kb + (64 * QPH) * 4;
#pragma unroll
        for (int u = 0; u < 4; u++) {
            int idx = u * 128 + tid;
            int r = idx >> 3, seg = idx & 7;
            cp_async16(kb + (r * QPH + seg * 4) * 4,
                       gk + hbase + (size_t)(t * 64 + r) * DIMM + seg * 8);
            cp_async16(vb + (r * VPH + seg * 4) * 4,
                       gv + hbase + (size_t)(t * 64 + r) * DIMM + seg * 8);
        }
        CP_COMMIT();
    };

    load_kv(0);
    if (qb >= 1) load_kv(1); else CP_COMMIT();

    // Q fragments straight from gmem
    const int arow = wid * 16 + r0;
    const uint32_t* qrow0 = (const uint32_t*)(gq + hbase + (size_t)(qb * 64 + arow) * DIMM);
    const uint32_t* qrow1 = (const uint32_t*)(gq + hbase + (size_t)(qb * 64 + arow + 8) * DIMM);
    uint32_t qf[4][4];
#pragma unroll
    for (int ks = 0; ks < 4; ks++) {
        qf[ks][0] = qrow0[ks * 8 + q4];
        qf[ks][1] = qrow1[ks * 8 + q4];
        qf[ks][2] = qrow0[ks * 8 + q4 + 4];
        qf[ks][3] = qrow1[ks * 8 + q4 + 4];
    }

    float o[8][4];
#pragma unroll
    for (int j = 0; j < 8; j++)
#pragma unroll
        for (int u = 0; u < 4; u++) o[j][u] = 0.f;
    float l0 = 0.f, l1 = 0.f;    // PER-LANE partials; reduced after the loop

    const int grow0 = qb * 64 + arow;
    const int grow1 = grow0 + 8;

    for (int t = 0; t <= qb; t++) {
        CP_WAIT(1);
        __syncthreads();
        if (t + 2 <= qb) load_kv(t + 2); else CP_COMMIT();

        const uint32_t kbase = sbase + ((t % 3) * FSW) * 4;
        const uint32_t vbase = kbase + (64 * QPH) * 4;

        // ---- S = Q @ K^T ----
        float c[8][4];
#pragma unroll
        for (int j = 0; j < 8; j++)
#pragma unroll
            for (int u = 0; u < 4; u++) c[j][u] = 0.f;

#pragma unroll
        for (int ks = 0; ks < 4; ks++) {
            uint32_t bf[8][2];
#pragma unroll
            for (int jp = 0; jp < 4; jp++)
                ldsm4(bf[2*jp][0], bf[2*jp][1], bf[2*jp+1][0], bf[2*jp+1][1],
                      kbase + koff_b + (jp * 16 * QPH + ks * 8) * 4);
#pragma unroll
            for (int j = 0; j < 8; j++)
                mma16(c[j], qf[ks], bf[j]);
        }

        // ---- causal mask + exp + per-lane partial sums ----
        const bool diag = (t == qb);
#pragma unroll
        for (int j = 0; j < 8; j++) {
            int col = t * 64 + j * 8 + 2 * q4;
            if (diag) {
                if (col     > grow0) c[j][0] = -1e9f;
                if (col + 1 > grow0) c[j][1] = -1e9f;
                if (col     > grow1) c[j][2] = -1e9f;
                if (col + 1 > grow1) c[j][3] = -1e9f;
            }
            c[j][0] = fexp_s(c[j][0]);
            c[j][1] = fexp_s(c[j][1]);
            c[j][2] = fexp_s(c[j][2]);
            c[j][3] = fexp_s(c[j][3]);
            l0 += c[j][0] + c[j][1];
            l1 += c[j][2] + c[j][3];
        }

        // ---- O += P @ V : P packed directly from S registers ----
#pragma unroll
        for (int ks = 0; ks < 4; ks++) {
            uint32_t a[4], bf[8][2];
            a[0] = pack_h2(c[2*ks][0],   c[2*ks][1]);
            a[1] = pack_h2(c[2*ks][2],   c[2*ks][3]);
            a[2] = pack_h2(c[2*ks+1][0], c[2*ks+1][1]);
            a[3] = pack_h2(c[2*ks+1][2], c[2*ks+1][3]);
#pragma unroll
            for (int jp = 0; jp < 4; jp++)
                ldsm4t(bf[2*jp][0], bf[2*jp][1], bf[2*jp+1][0], bf[2*jp+1][1],
                       vbase + voff_b + (ks * 16 * VPH + jp * 8) * 4);
#pragma unroll
            for (int j = 0; j < 8; j++)
                mma16(o[j], a, bf[j]);
        }
    }

    // ---- one-time row-sum reduction ----
    l0 += __shfl_xor_sync(0xffffffffu, l0, 1);
    l0 += __shfl_xor_sync(0xffffffffu, l0, 2);
    l1 += __shfl_xor_sync(0xffffffffu, l1, 1);
    l1 += __shfl_xor_sync(0xffffffffu, l1, 2);

    // ---- normalize + store as half ----
    const float inv0 = 1.f / l0, inv1 = 1.f / l1;
    const int row0 = qb * 64 + arow;
#pragma unroll
    for (int j = 0; j < 8; j++) {
        int col = j * 8 + 2 * q4;
        __half* p0 = go + hbase + (size_t)row0 * DIMM + col;
        *(uint32_t*)p0              = pack_h2(o[j][0] * inv0, o[j][1] * inv0);
        *(uint32_t*)(p0 + 8 * DIMM) = pack_h2(o[j][2] * inv1, o[j][3] * inv1);
    }
}

// ===========================================================================
extern "C" void kernel_launch(void* const* d_in, const int* in_sizes, int n_in,
                              void* d_out, int out_size)
{
    (void)in_sizes; (void)n_in; (void)out_size;
    const float* x  = (const float*)d_in[0];
    const float* wq = (const float*)d_in[2];
    const float* wk = (const float*)d_in[3];
    const float* wv = (const float*)d_in[4];
    const float* wo = (const float*)d_in[5];
    float* out = (float*)d_out;

    __half *qh, *kh, *vh, *att, *xh, *wh;
    cudaGetSymbolAddress((void**)&qh,  g_qh);
    cudaGetSymbolAddress((void**)&kh,  g_kh);
    cudaGetSymbolAddress((void**)&vh,  g_vh);
    cudaGetSymbolAddress((void**)&att, g_att);
    cudaGetSymbolAddress((void**)&xh,  g_xh);
    cudaGetSymbolAddress((void**)&wh,  g_wh);

    cudaFuncSetAttribute(gemm_h<true>,  cudaFuncAttributeMaxDynamicSharedMemorySize, GSMEM_BYTES);
    cudaFuncSetAttribute(gemm_h<false>, cudaFuncAttributeMaxDynamicSharedMemorySize, GSMEM_BYTES);
    cudaFuncSetAttribute(flash_h,       cudaFuncAttributeMaxDynamicSharedMemorySize, FSMEM_BYTES);

    const int xn4 = MROWS * DIMM / 4;    // 1,048,576
    const int wn4 = WFLOATS / 4;         // 262,144
    round_all<<<dim3(xn4 / 256, 5), 256>>>(x, wq, wk, wv, wo, xh, wh, xn4, wn4);

    gemm_h<true><<<dim3(DIMM / 128, MROWS / 128, 3), 256, GSMEM_BYTES>>>(
        xh, wh + 0 * WFLOATS, wh + 1 * WFLOATS, wh + 2 * WFLOATS, qh, kh, vh);

    flash_h<<<dim3(SEQ / 64, BATCH * NHEADS), 128, FSMEM_BYTES>>>(qh, kh, vh, att);

    gemm_h<false><<<dim3(DIMM / 128, MROWS / 128, 1), 256, GSMEM_BYTES>>>(
        att, wh + 3 * WFLOATS, wh + 3 * WFLOATS, wh + 3 * WFLOATS, out, out, out);
}

// round 15
// speedup vs baseline: 1.0017x; 1.0017x over previous
#include <cuda_runtime.h>
#include <cuda_fp16.h>
#include <cstdint>

#define DIMM   1024
#define NHEADS 16
#define HD     64
#define BATCH  2
#define SEQ    2048
#define MROWS  (BATCH*SEQ)   /* 4096 */
#define WFLOATS (DIMM*DIMM)

// Scratch (allocation-free)
__device__ __half g_qh[MROWS*DIMM];
__device__ __half g_kh[MROWS*DIMM];
__device__ __half g_vh[MROWS*DIMM];
__device__ __half g_att[MROWS*DIMM];
__device__ __half g_xh[MROWS*DIMM];
__device__ __half g_wh[4*WFLOATS];

// ===========================================================================
// Helpers
// ===========================================================================
__device__ __forceinline__ uint32_t smem_u32(const void* p) {
    uint32_t a;
    asm("{ .reg .u64 t; cvta.to.shared.u64 t, %1; cvt.u32.u64 %0, t; }" : "=r"(a) : "l"(p));
    return a;
}
__device__ __forceinline__ void cp_async16(uint32_t dst, const void* src) {
    asm volatile("cp.async.cg.shared.global [%0], [%1], 16;" :: "r"(dst), "l"(src) : "memory");
}
#define CP_COMMIT()  asm volatile("cp.async.commit_group;" ::: "memory")
#define CP_WAIT(n)   asm volatile("cp.async.wait_group %0;" :: "n"(n) : "memory")

__device__ __forceinline__ uint32_t pack_h2(float a, float b) {
    __half2 h = __floats2half2_rn(a, b);
    return *(uint32_t*)&h;
}
// fp16 m16n8k16: D += A*B
__device__ __forceinline__ void mma16(float* c, const uint32_t* a, const uint32_t* b) {
    asm volatile(
        "mma.sync.aligned.m16n8k16.row.col.f32.f16.f16.f32 "
        "{%0,%1,%2,%3}, {%4,%5,%6,%7}, {%8,%9}, {%0,%1,%2,%3};"
        : "+f"(c[0]), "+f"(c[1]), "+f"(c[2]), "+f"(c[3])
        : "r"(a[0]), "r"(a[1]), "r"(a[2]), "r"(a[3]), "r"(b[0]), "r"(b[1]));
}
__device__ __forceinline__ void ldsm4(uint32_t& r0, uint32_t& r1, uint32_t& r2, uint32_t& r3,
                                      uint32_t addr) {
    asm volatile("ldmatrix.sync.aligned.m8n8.x4.shared.b16 {%0,%1,%2,%3}, [%4];"
                 : "=r"(r0), "=r"(r1), "=r"(r2), "=r"(r3) : "r"(addr));
}
__device__ __forceinline__ void ldsm4t(uint32_t& r0, uint32_t& r1, uint32_t& r2, uint32_t& r3,
                                       uint32_t addr) {
    asm volatile("ldmatrix.sync.aligned.m8n8.x4.trans.shared.b16 {%0,%1,%2,%3}, [%4];"
                 : "=r"(r0), "=r"(r1), "=r"(r2), "=r"(r3) : "r"(addr));
}

// FMA-pipe exp: e^(s * 0.125). Clamps low (masked entries -> ~0).
__device__ __forceinline__ float fexp_s(float s) {
    float y = s * 0.18033688011112042f;
    y = fmaxf(y, -100.0f);
    float t = __fadd_rn(y, 12582912.0f);
    float f = __fsub_rn(y, __fsub_rn(t, 12582912.0f));
    int   e = __float_as_int(t) << 23;
    float p = 1.3333558146e-3f;
    p = fmaf(p, f, 9.618129107e-3f);
    p = fmaf(p, f, 5.550410866e-2f);
    p = fmaf(p, f, 2.402265069e-1f);
    p = fmaf(p, f, 6.931471806e-1f);
    p = fmaf(p, f, 1.0f);
    return __int_as_float(__float_as_int(p) + e);
}

// ===========================================================================
// Fused fp32 -> fp16 conversion: y=0 -> x (n4x), y=1..4 -> weights (n4w each)
// ===========================================================================
__global__ __launch_bounds__(256) void round_all(
    const float* __restrict__ x,
    const float* __restrict__ w0, const float* __restrict__ w1,
    const float* __restrict__ w2, const float* __restrict__ w3,
    __half* __restrict__ xh, __half* __restrict__ wh, int n4x, int n4w)
{
    const int y = blockIdx.y;
    const float* in;
    __half* o;
    int n4;
    if (y == 0) { in = x; o = xh; n4 = n4x; }
    else        { in = (y == 1) ? w0 : (y == 2) ? w1 : (y == 3) ? w2 : w3;
                  o = wh + (size_t)(y - 1) * WFLOATS; n4 = n4w; }
    int i = blockIdx.x * blockDim.x + threadIdx.x;
    if (i < n4) {
        float4 v = ((const float4*)in)[i];
        uint2 w;
        w.x = pack_h2(v.x, v.y);
        w.y = pack_h2(v.z, v.w);
        ((uint2*)o)[i] = w;
    }
}

// ===========================================================================
// fp16 mma.sync GEMM with ldmatrix fragments.
// CTA 128x128, 8 warps (2m x 4n), BK=32 halves, 3-stage cp.async,
// SINGLE barrier per ktile.
// ===========================================================================
#define BK    32
#define KW    20
#define GST   3
#define GSTAGE_U32 (2*128*KW)
#define GSMEM_BYTES (GST * GSTAGE_U32 * 4)   /* 61440 */
#define KT    (DIMM / BK)

template<bool HALF_OUT>
__global__ __launch_bounds__(256, 2) void gemm_h(
    const __half* __restrict__ A,
    const __half* __restrict__ B0, const __half* __restrict__ B1, const __half* __restrict__ B2,
    void* __restrict__ C0, void* __restrict__ C1, void* __restrict__ C2)
{
    extern __shared__ uint32_t sm[];
    const int tid  = threadIdx.x;
    const int wid  = tid >> 5;
    const int lane = tid & 31;
    const int wm   = wid >> 2;
    const int wn   = wid & 3;
    const int r0   = lane >> 2;
    const int q4   = lane & 3;
    const int g    = lane >> 3;
    const int lr   = lane & 7;

    const __half* Bz = (blockIdx.z == 0) ? B0 : (blockIdx.z == 1) ? B1 : B2;
    void*         Cz = (blockIdx.z == 0) ? C0 : (blockIdx.z == 1) ? C1 : C2;

    const __half* Ag = A  + (size_t)(blockIdx.y * 128) * DIMM;
    const __half* Bg = Bz + (size_t)(blockIdx.x * 128) * DIMM;
    const uint32_t sbase = smem_u32(sm);

    const uint32_t a_off = ((wm * 64 + (g & 1) * 8 + lr) * KW + (g >> 1) * 4) * 4;
    const uint32_t b_off = (128 * KW + (wn * 32 + (g >> 1) * 8 + lr) * KW + (g & 1) * 4) * 4;

    auto load_tile = [&](int kt) {
        const int s = kt % GST;
        uint32_t ab = sbase + s * GSTAGE_U32 * 4;
        uint32_t bb = ab + 128 * KW * 4;
#pragma unroll
        for (int i = 0; i < 2; i++) {
            int idx = i * 256 + tid;
            int row = idx >> 2, seg = idx & 3;
            cp_async16(ab + (row * KW + seg * 4) * 4,
                       Ag + (size_t)row * DIMM + kt * BK + seg * 8);
        }
#pragma unroll
        for (int i = 0; i < 2; i++) {
            int idx = i * 256 + tid;
            int row = idx >> 2, seg = idx & 3;
            cp_async16(bb + (row * KW + seg * 4) * 4,
                       Bg + (size_t)row * DIMM + kt * BK + seg * 8);
        }
        CP_COMMIT();
    };

    float c[4][4][4];
#pragma unroll
    for (int i = 0; i < 4; i++)
#pragma unroll
        for (int j = 0; j < 4; j++)
#pragma unroll
            for (int u = 0; u < 4; u++) c[i][j][u] = 0.f;

    load_tile(0);
    load_tile(1);

    for (int kt = 0; kt < KT; kt++) {
        if (kt + 1 < KT) { CP_WAIT(1); } else { CP_WAIT(0); }
        __syncthreads();     // kt resident for all warps; all warps done reading stage (kt+2)%3
        if (kt + 2 < KT) load_tile(kt + 2);

        const uint32_t stage = sbase + (kt % GST) * GSTAGE_U32 * 4;
#pragma unroll
        for (int st = 0; st < 2; st++) {
            const uint32_t koff = st * 8 * 4;
            uint32_t a[4][4], b[4][2];
#pragma unroll
            for (int i = 0; i < 4; i++)
                ldsm4(a[i][0], a[i][1], a[i][2], a[i][3],
                      stage + a_off + (i * 16 * KW) * 4 + koff);
#pragma unroll
            for (int jp = 0; jp < 2; jp++)
                ldsm4(b[2*jp][0], b[2*jp][1], b[2*jp+1][0], b[2*jp+1][1],
                      stage + b_off + (jp * 16 * KW) * 4 + koff);
#pragma unroll
            for (int i = 0; i < 4; i++)
#pragma unroll
                for (int j = 0; j < 4; j++)
                    mma16(c[i][j], a[i], b[j]);
        }
    }

    const size_t crow = (size_t)(blockIdx.y * 128 + wm * 64);
    const int    ccol = blockIdx.x * 128 + wn * 32;
#pragma unroll
    for (int i = 0; i < 4; i++)
#pragma unroll
        for (int j = 0; j < 4; j++) {
            int lrr = i * 16 + r0;
            int col = j * 8 + 2 * q4;
            if (HALF_OUT) {
                __half* Ch = (__half*)Cz + (crow + lrr) * DIMM + ccol + col;
                *(uint32_t*)Ch              = pack_h2(c[i][j][0], c[i][j][1]);
                *(uint32_t*)(Ch + 8 * DIMM) = pack_h2(c[i][j][2], c[i][j][3]);
            } else {
                float* Cf = (float*)Cz + (crow + lrr) * DIMM + ccol + col;
                *(float2*)Cf              = make_float2(c[i][j][0], c[i][j][1]);
                *(float2*)(Cf + 8 * DIMM) = make_float2(c[i][j][2], c[i][j][3]);
            }
        }
}

// ===========================================================================
// Fused causal flash attention, all-fp16, register-P, 3-stage KV ring,
// one barrier per tile, DEFERRED row-sum reduction (outside the loop).
// ===========================================================================
#define QPH 36
#define VPH 36
#define FSW  (2*64*QPH)
#define FSMEM_WORDS (3*FSW)
#define FSMEM_BYTES (FSMEM_WORDS * 4)   /* 55296 */

__global__ __launch_bounds__(128, 4) void flash_h(
    const __half* __restrict__ gq, const __half* __restrict__ gk,
    const __half* __restrict__ gv, __half* __restrict__ go)
{
    extern __shared__ uint32_t fsm[];

    const int qb  = gridDim.x - 1 - blockIdx.x;
    const int bh  = blockIdx.y;
    const int b   = bh >> 4;
    const int h   = bh & 15;
    const int tid = threadIdx.x;
    const int wid = tid >> 5;
    const int lane = tid & 31;
    const int r0 = lane >> 2;
    const int q4 = lane & 3;
    const int g  = lane >> 3;
    const int lr = lane & 7;
    const size_t hbase = (size_t)b * SEQ * DIMM + (size_t)h * HD;
    const uint32_t sbase = smem_u32(fsm);

    const uint32_t koff_b = (((g >> 1) * 8 + lr) * QPH + (g & 1) * 4) * 4;
    const uint32_t voff_b = (((g & 1) * 8 + lr) * VPH + (g >> 1) * 4) * 4;

    auto load_kv = [&](int t) {
        const int s = t % 3;
        const uint32_t kb = sbase + (s * FSW) * 4;
        const uint32_t vb = kb + (64 * QPH) * 4;
#pragma unroll
        for (int u = 0; u < 4; u++) {
            int idx = u * 128 + tid;
            int r = idx >> 3, seg = idx & 7;
            cp_async16(kb + (r * QPH + seg * 4) * 4,
                       gk + hbase + (size_t)(t * 64 + r) * DIMM + seg * 8);
            cp_async16(vb + (r * VPH + seg * 4) * 4,
                       gv + hbase + (size_t)(t * 64 + r) * DIMM + seg * 8);
        }
        CP_COMMIT();
    };

    load_kv(0);
    if (qb >= 1) load_kv(1); else CP_COMMIT();

    // Q fragments straight from gmem
    const int arow = wid * 16 + r0;
    const uint32_t* qrow0 = (const uint32_t*)(gq + hbase + (size_t)(qb * 64 + arow) * DIMM);
    const uint32_t* qrow1 = (const uint32_t*)(gq + hbase + (size_t)(qb * 64 + arow + 8) * DIMM);
    uint32_t qf[4][4];
#pragma unroll
    for (int ks = 0; ks < 4; ks++) {
        qf[ks][0] = qrow0[ks * 8 + q4];
        qf[ks][1] = qrow1[ks * 8 + q4];
        qf[ks][2] = qrow0[ks * 8 + q4 + 4];
        qf[ks][3] = qrow1[ks * 8 + q4 + 4];
    }

    float o[8][4];
#pragma unroll
    for (int j = 0; j < 8; j++)
#pragma unroll
        for (int u = 0; u < 4; u++) o[j][u] = 0.f;
    float l0 = 0.f, l1 = 0.f;    // PER-LANE partials; reduced after the loop

    const int grow0 = qb * 64 + arow;
    const int grow1 = grow0 + 8;

    for (int t = 0; t <= qb; t++) {
        CP_WAIT(1);
        __syncthreads();
        if (t + 2 <= qb) load_kv(t + 2); else CP_COMMIT();

        const uint32_t kbase = sbase + ((t % 3) * FSW) * 4;
        const uint32_t vbase = kbase + (64 * QPH) * 4;

        // ---- S = Q @ K^T ----
        float c[8][4];
#pragma unroll
        for (int j = 0; j < 8; j++)
#pragma unroll
            for (int u = 0; u < 4; u++) c[j][u] = 0.f;

#pragma unroll
        for (int ks = 0; ks < 4; ks++) {
            uint32_t bf[8][2];
#pragma unroll
            for (int jp = 0; jp < 4; jp++)
                ldsm4(bf[2*jp][0], bf[2*jp][1], bf[2*jp+1][0], bf[2*jp+1][1],
                      kbase + koff_b + (jp * 16 * QPH + ks * 8) * 4);
#pragma unroll
            for (int j = 0; j < 8; j++)
                mma16(c[j], qf[ks], bf[j]);
        }

        // ---- causal mask + exp + per-lane partial sums ----
        const bool diag = (t == qb);
#pragma unroll
        for (int j = 0; j < 8; j++) {
            int col = t * 64 + j * 8 + 2 * q4;
            if (diag) {
                if (col     > grow0) c[j][0] = -1e9f;
                if (col + 1 > grow0) c[j][1] = -1e9f;
                if (col     > grow1) c[j][2] = -1e9f;
                if (col + 1 > grow1) c[j][3] = -1e9f;
            }
            c[j][0] = fexp_s(c[j][0]);
            c[j][1] = fexp_s(c[j][1]);
            c[j][2] = fexp_s(c[j][2]);
            c[j][3] = fexp_s(c[j][3]);
            l0 += c[j][0] + c[j][1];
            l1 += c[j][2] + c[j][3];
        }

        // ---- O += P @ V : P packed directly from S registers ----
#pragma unroll
        for (int ks = 0; ks < 4; ks++) {
            uint32_t a[4], bf[8][2];
            a[0] = pack_h2(c[2*ks][0],   c[2*ks][1]);
            a[1] = pack_h2(c[2*ks][2],   c[2*ks][3]);
            a[2] = pack_h2(c[2*ks+1][0], c[2*ks+1][1]);
            a[3] = pack_h2(c[2*ks+1][2], c[2*ks+1][3]);
#pragma unroll
            for (int jp = 0; jp < 4; jp++)
                ldsm4t(bf[2*jp][0], bf[2*jp][1], bf[2*jp+1][0], bf[2*jp+1][1],
                       vbase + voff_b + (ks * 16 * VPH + jp * 8) * 4);
#pragma unroll
            for (int j = 0; j < 8; j++)
                mma16(o[j], a, bf[j]);
        }
    }

    // ---- one-time row-sum reduction ----
    l0 += __shfl_xor_sync(0xffffffffu, l0, 1);
    l0 += __shfl_xor_sync(0xffffffffu, l0, 2);
    l1 += __shfl_xor_sync(0xffffffffu, l1, 1);
    l1 += __shfl_xor_sync(0xffffffffu, l1, 2);

    // ---- normalize + store as half ----
    const float inv0 = 1.f / l0, inv1 = 1.f / l1;
    const int row0 = qb * 64 + arow;
#pragma unroll
    for (int j = 0; j < 8; j++) {
        int col = j * 8 + 2 * q4;
        __half* p0 = go + hbase + (size_t)row0 * DIMM + col;
        *(uint32_t*)p0              = pack_h2(o[j][0] * inv0, o[j][1] * inv0);
        *(uint32_t*)(p0 + 8 * DIMM) = pack_h2(o[j][2] * inv1, o[j][3] * inv1);
    }
}

// ===========================================================================
extern "C" void kernel_launch(void* const* d_in, const int* in_sizes, int n_in,
                              void* d_out, int out_size)
{
    (void)in_sizes; (void)n_in; (void)out_size;
    const float* x  = (const float*)d_in[0];
    const float* wq = (const float*)d_in[2];
    const float* wk = (const float*)d_in[3];
    const float* wv = (const float*)d_in[4];
    const float* wo = (const float*)d_in[5];
    float* out = (float*)d_out;

    __half *qh, *kh, *vh, *att, *xh, *wh;
    cudaGetSymbolAddress((void**)&qh,  g_qh);
    cudaGetSymbolAddress((void**)&kh,  g_kh);
    cudaGetSymbolAddress((void**)&vh,  g_vh);
    cudaGetSymbolAddress((void**)&att, g_att);
    cudaGetSymbolAddress((void**)&xh,  g_xh);
    cudaGetSymbolAddress((void**)&wh,  g_wh);

    cudaFuncSetAttribute(gemm_h<true>,  cudaFuncAttributeMaxDynamicSharedMemorySize, GSMEM_BYTES);
    cudaFuncSetAttribute(gemm_h<false>, cudaFuncAttributeMaxDynamicSharedMemorySize, GSMEM_BYTES);
    cudaFuncSetAttribute(flash_h,       cudaFuncAttributeMaxDynamicSharedMemorySize, FSMEM_BYTES);

    const int xn4 = MROWS * DIMM / 4;    // 1,048,576
    const int wn4 = WFLOATS / 4;         // 262,144
    round_all<<<dim3(xn4 / 256, 5), 256>>>(x, wq, wk, wv, wo, xh, wh, xn4, wn4);

    gemm_h<true><<<dim3(DIMM / 128, MROWS / 128, 3), 256, GSMEM_BYTES>>>(
        xh, wh + 0 * WFLOATS, wh + 1 * WFLOATS, wh + 2 * WFLOATS, qh, kh, vh);

    flash_h<<<dim3(SEQ / 64, BATCH * NHEADS), 128, FSMEM_BYTES>>>(qh, kh, vh, att);

    gemm_h<false><<<dim3(DIMM / 128, MROWS / 128, 1), 256, GSMEM_BYTES>>>(
        att, wh + 3 * WFLOATS, wh + 3 * WFLOATS, wh + 3 * WFLOATS, out, out, out);
}